// round 17
// baseline (speedup 1.0000x reference)
#include <cuda_runtime.h>
#include <cuda_fp16.h>
#include <cstdint>

// Problem constants
#define BB   2
#define TT   2048
#define DDIM 1024
#define HH   16
#define HDD  64
#define MM   (BB*TT)   // 4096 rows
#define DKK  64        // attention Q/K/V dim

// Scratch (__device__ globals; no allocations allowed)
__device__ __half g_xh[MM*DDIM];
__device__ __half g_atts[MM*DDIM];
__device__ __half g_w16[3*DDIM*DDIM];    // [Wq | Wk | Wv] fp16 planes
__device__ __half g_wo16[DDIM*DDIM];
__device__ __half g_qp[BB*HH*TT*DKK];
__device__ __half g_kp[BB*HH*TT*DKK];
__device__ __half g_vp[BB*HH*TT*DKK];

// ---------------------------------------------------------------------------
__device__ __forceinline__ uint32_t s2u(const void* p) {
    uint32_t a;
    asm("{ .reg .u64 t; cvta.to.shared.u64 t, %1; cvt.u32.u64 %0, t; }" : "=r"(a) : "l"(p));
    return a;
}
__device__ __forceinline__ uint32_t swz(uint32_t o) { return o ^ ((o >> 3) & 0x70); }
__device__ __forceinline__ void cp16(uint32_t dst, const void* src) {
    asm volatile("cp.async.cg.shared.global [%0], [%1], 16;" :: "r"(dst), "l"(src));
}
__device__ __forceinline__ void ldsm4(uint32_t* r, uint32_t addr) {
    asm volatile("ldmatrix.sync.aligned.m8n8.x4.shared.b16 {%0,%1,%2,%3}, [%4];"
                 : "=r"(r[0]), "=r"(r[1]), "=r"(r[2]), "=r"(r[3]) : "r"(addr));
}
__device__ __forceinline__ void ldsm4t(uint32_t* r, uint32_t addr) {
    asm volatile("ldmatrix.sync.aligned.m8n8.x4.trans.shared.b16 {%0,%1,%2,%3}, [%4];"
                 : "=r"(r[0]), "=r"(r[1]), "=r"(r[2]), "=r"(r[3]) : "r"(addr));
}
__device__ __forceinline__ void mma16816(float* c, const uint32_t* a, const uint32_t* b) {
    asm volatile("mma.sync.aligned.m16n8k16.row.col.f32.f16.f16.f32 "
                 "{%0,%1,%2,%3}, {%4,%5,%6,%7}, {%8,%9}, {%0,%1,%2,%3};"
                 : "+f"(c[0]), "+f"(c[1]), "+f"(c[2]), "+f"(c[3])
                 : "r"(a[0]), "r"(a[1]), "r"(a[2]), "r"(a[3]), "r"(b[0]), "r"(b[1]));
}
__device__ __forceinline__ float ex2(float x) {
    float y; asm("ex2.approx.f32 %0, %1;" : "=f"(y) : "f"(x)); return y;
}
// pack (lo,hi) fp32 -> f16x2 then exponentiate both lanes
__device__ __forceinline__ uint32_t ex2_pack(float lo, float hi) {
    uint32_t u;
    asm("cvt.rn.f16x2.f32 %0, %1, %2;" : "=r"(u) : "f"(hi), "f"(lo));
    asm("ex2.approx.f16x2 %0, %0;" : "+r"(u));
    return u;
}

// ---------------------------------------------------------------------------
// xconv: fp32 x [4096,1024] -> fp16 single plane
// ---------------------------------------------------------------------------
__global__ __launch_bounds__(256) void xconv(const float* __restrict__ in,
                                             __half* __restrict__ out) {
    int idx = (blockIdx.x * 256 + threadIdx.x) * 4;
    float4 v = *(const float4*)(in + idx);
    __half2 a{__float2half_rn(v.x), __float2half_rn(v.y)};
    __half2 b{__float2half_rn(v.z), __float2half_rn(v.w)};
    *(uint32_t*)(out + idx)     = *(uint32_t*)&a;
    *(uint32_t*)(out + idx + 2) = *(uint32_t*)&b;
}

// wconv4: Wq/Wk/Wv -> merged fp16 buffer; Wo -> own plane. One launch.
__global__ __launch_bounds__(256) void wconv4(const float* __restrict__ w0,
                                              const float* __restrict__ w1,
                                              const float* __restrict__ w2,
                                              const float* __restrict__ w3,
                                              __half* __restrict__ wqkv,
                                              __half* __restrict__ wo) {
    const float* in; __half* out;
    switch (blockIdx.y) {
        case 0: in = w0; out = wqkv; break;
        case 1: in = w1; out = wqkv + DDIM*DDIM; break;
        case 2: in = w2; out = wqkv + 2*DDIM*DDIM; break;
        default: in = w3; out = wo; break;
    }
    int idx = (blockIdx.x * 256 + threadIdx.x) * 4;
    float4 v = *(const float4*)(in + idx);
    __half2 a{__float2half_rn(v.x), __float2half_rn(v.y)};
    __half2 b{__float2half_rn(v.z), __float2half_rn(v.w)};
    *(uint32_t*)(out + idx)     = *(uint32_t*)&a;
    *(uint32_t*)(out + idx + 2) = *(uint32_t*)&b;
}

// ---------------------------------------------------------------------------
// fp16 HMMA NT GEMM, K=1024 single plane (16 chunks).
// CTA 128x128, 8 warps (2x4), warp tile 64x32, BK=64, 3-stage cp.async,
// 2 CTAs/SM (16 warps/SM; launch_bounds caps regs at 128).
// mode 0: fp32 C out.  mode 3: merged QKV — sect 0 Q (x 0.125*log2e), 1 K, 2 V.
// ---------------------------------------------------------------------------
#define BK      64
#define STAGES  3
#define NCHUNK  (DDIM / BK)               // 16
#define STG_A   (128 * 128)               // 16 KB
#define STG_B   (128 * 128)               // 16 KB
#define STG_SZ  (STG_A + STG_B)           // 32 KB
#define GEMM_DYN (STAGES * STG_SZ + 1024) // ~97 KB
#define QSCALE  0.180336880111f           // 0.125 * log2(e)

__global__ __launch_bounds__(256, 2) void gemm_hmma(const __half* __restrict__ A,
                                                    const __half* __restrict__ B,
                                                    void* __restrict__ Cout, int mode) {
    extern __shared__ char dyn[];
    const int tid  = threadIdx.x;
    const int wid  = tid >> 5, lane = tid & 31;
    const int wm   = wid >> 2;            // 0..1 (64-row slab)
    const int wn   = wid & 3;             // 0..3 (32-col slab)
    const int m0   = blockIdx.y << 7;
    const int n0   = blockIdx.x << 7;

    const uint32_t sbase = (s2u(dyn) + 1023) & ~1023u;
    const int lrow = tid >> 3;            // 0..31 base load row
    const int ls16 = tid & 7;

    float acc[4][4][4];
#pragma unroll
    for (int mi = 0; mi < 4; mi++)
#pragma unroll
        for (int ni = 0; ni < 4; ni++)
#pragma unroll
            for (int j = 0; j < 4; j++) acc[mi][ni][j] = 0.f;

    const int sub  = lane >> 3;
    const int lr8  = lane & 7;
    const int aRowOff = ((sub & 1) << 3) + lr8;
    const int aKHalf  = (sub >> 1) << 4;
    const int bRowOff = ((sub >> 1) << 3) + lr8;
    const int bKHalf  = (sub & 1) << 4;

    auto load_chunk = [&](int c) {
        const int s_ = c % STAGES;
        const uint32_t sA_ = sbase + s_ * STG_SZ;
        const uint32_t sB_ = sA_ + STG_A;
#pragma unroll
        for (int it = 0; it < 4; it++) {
            int row = lrow + (it << 5);
            cp16(sA_ + swz(row * 128 + ls16 * 16),
                 A + (size_t)(m0 + row) * DDIM + c * BK + ls16 * 8);
        }
#pragma unroll
        for (int it = 0; it < 4; it++) {
            int row = lrow + (it << 5);
            cp16(sB_ + swz(row * 128 + ls16 * 16),
                 B + (size_t)(n0 + row) * DDIM + c * BK + ls16 * 8);
        }
        asm volatile("cp.async.commit_group;" ::: "memory");
    };

    load_chunk(0);
    load_chunk(1);

    for (int i = 0; i < NCHUNK; i++) {
        if (i < NCHUNK - 1) asm volatile("cp.async.wait_group 1;" ::: "memory");
        else                asm volatile("cp.async.wait_group 0;" ::: "memory");
        __syncthreads();

        if (i + 2 < NCHUNK) load_chunk(i + 2);

        const int s = i % STAGES;
        const uint32_t sA = sbase + s * STG_SZ;
        const uint32_t sB = sA + STG_A;

#pragma unroll
        for (int kk = 0; kk < 4; kk++) {
            uint32_t af[4][4], bf[2][4];
#pragma unroll
            for (int mi = 0; mi < 4; mi++) {
                int row = wm * 64 + mi * 16 + aRowOff;
                ldsm4(af[mi], sA + swz(row * 128 + kk * 32 + aKHalf));
            }
#pragma unroll
            for (int p = 0; p < 2; p++) {
                int row = wn * 32 + p * 16 + bRowOff;
                ldsm4(bf[p], sB + swz(row * 128 + kk * 32 + bKHalf));
            }
#pragma unroll
            for (int mi = 0; mi < 4; mi++)
#pragma unroll
                for (int nj = 0; nj < 4; nj++)
                    mma16816(acc[mi][nj], af[mi], &bf[nj >> 1][(nj & 1) * 2]);
        }
    }

    const int lr = lane >> 2, lc = (lane & 3) << 1;
    if (mode == 0) {
        float* C = (float*)Cout;
#pragma unroll
        for (int mi = 0; mi < 4; mi++)
#pragma unroll
            for (int nj = 0; nj < 4; nj++) {
                int grow = m0 + wm * 64 + mi * 16 + lr;
                int gcol = n0 + wn * 32 + nj * 8 + lc;
                *(float2*)&C[(size_t)grow * DDIM + gcol] =
                    make_float2(acc[mi][nj][0], acc[mi][nj][1]);
                *(float2*)&C[(size_t)(grow + 8) * DDIM + gcol] =
                    make_float2(acc[mi][nj][2], acc[mi][nj][3]);
            }
    } else {
        const int sect = n0 >> 10;                // 0=Q, 1=K, 2=V
        const float sc = (sect == 0) ? QSCALE : 1.f;
        const int nbase = n0 & 1023;
        __half* P = (sect == 0) ? g_qp : (sect == 1) ? g_kp : g_vp;
#pragma unroll
        for (int mi = 0; mi < 4; mi++)
#pragma unroll
            for (int nj = 0; nj < 4; nj++) {
                int grow = m0 + wm * 64 + mi * 16 + lr;
                int coln = wn * 32 + nj * 8 + lc;
                int hh   = (nbase >> 6) + (coln >> 6);
                int d    = coln & 63;
#pragma unroll
                for (int half_ = 0; half_ < 2; half_++) {
                    int row = grow + half_ * 8;
                    int b = row >> 11, t = row & 2047;
                    float v0 = acc[mi][nj][half_ * 2] * sc;
                    float v1 = acc[mi][nj][half_ * 2 + 1] * sc;
                    __half2 hp{__float2half_rn(v0), __float2half_rn(v1)};
                    size_t base = ((size_t)(b * HH + hh) * TT + t) * DKK + d;
                    *(uint32_t*)(P + base) = *(uint32_t*)&hp;
                }
            }
    }
}

// ---------------------------------------------------------------------------
// fp16 flash attention, KV tile 128. log2-domain softmax with f16x2 ex2
// (P produced directly in A-frag layout); row-sum via ones-column MMA;
// V via trans-ldmatrix. Writes single-plane fp16 atts.
// 128 threads (4 warps x 16 q-rows = 64 q-rows/CTA), 2-stage KV, 2 CTAs/SM.
// Heavy-first: qb = gridDim.x-1-blockIdx.x.
// ---------------------------------------------------------------------------
#define ATT_QSZ   8192                     // 64 x 128B (Q single plane)
#define ATT_STG   32768                    // K 16KB + V 16KB (128 kv rows)
#define ATT_DYN   (ATT_QSZ + 2*ATT_STG + 1024)   // ~74 KB

__global__ __launch_bounds__(128, 2) void attn_mma(const __half* __restrict__ Qp,
                                                   const __half* __restrict__ Kp,
                                                   const __half* __restrict__ Vp,
                                                   __half* __restrict__ Oout) {
    extern __shared__ char dyn[];
    const int tid = threadIdx.x, wid = tid >> 5, lane = tid & 31;
    const int qb = (int)(gridDim.x - 1 - blockIdx.x);   // heavy-first
    const int h = blockIdx.y, b = blockIdx.z;
    const int q0 = qb << 6;
    const int JT = (qb >> 1) + 1;          // 128-wide kv tiles

    const uint32_t sb = (s2u(dyn) + 1023) & ~1023u;
    const uint32_t QS = sb;
    const uint32_t ST0 = sb + ATT_QSZ;
    const uint32_t ST1 = ST0 + ATT_STG;

    const int sub = lane >> 3, lr8 = lane & 7;
    const int aRowOff = ((sub & 1) << 3) + lr8;   // also trans-ldsm row offset
    const int aKHalf  = (sub >> 1) << 4;          // also trans-ldsm col offset
    const int bRowOff = ((sub >> 1) << 3) + lr8;
    const int bKHalf  = (sub & 1) << 4;

    const size_t bh = (size_t)(b * HH + h);
    const __half* Qg = Qp + (bh * TT + q0) * DKK;
    const __half* Kg = Kp + bh * TT * DKK;
    const __half* Vg = Vp + bh * TT * DKK;

    // Q tile: 64 rows x 64 halfs = 512 cp16 / 128 threads = 4 iters
#pragma unroll
    for (int it = 0; it < 4; it++) {
        int idx = tid + it * 128;
        int row = idx >> 3, seg = idx & 7;
        cp16(QS + swz(row * 128 + seg * 16), Qg + (size_t)row * DKK + seg * 8);
    }
    asm volatile("cp.async.commit_group;" ::: "memory");

    auto load_kv = [&](int jt) {
        const uint32_t S = (jt & 1) ? ST1 : ST0;
        const int kv0 = jt << 7;
#pragma unroll
        for (int it = 0; it < 8; it++) {       // K [s][d] 128x128B
            int idx = tid + it * 128;
            int row = idx >> 3, seg = idx & 7;
            cp16(S + swz(row * 128 + seg * 16),
                 Kg + (size_t)(kv0 + row) * DKK + seg * 8);
        }
#pragma unroll
        for (int it = 0; it < 8; it++) {       // V [s][d] 128x128B
            int idx = tid + it * 128;
            int row = idx >> 3, seg = idx & 7;
            cp16(S + 16384 + swz(row * 128 + seg * 16),
                 Vg + (size_t)(kv0 + row) * DKK + seg * 8);
        }
        asm volatile("cp.async.commit_group;" ::: "memory");
    };
    load_kv(0);
    if (JT > 1) load_kv(1);

    // Q (+kv0) complete before ldsm; conditional on committed group count
    if (JT > 1) asm volatile("cp.async.wait_group 1;" ::: "memory");
    else        asm volatile("cp.async.wait_group 0;" ::: "memory");
    __syncthreads();

    uint32_t qa[4][4];
#pragma unroll
    for (int kk = 0; kk < 4; kk++) {
        int row = wid * 16 + aRowOff;
        ldsm4(qa[kk], QS + swz(row * 128 + kk * 32 + aKHalf));
    }

    float oc[8][4], ls[4];
#pragma unroll
    for (int j = 0; j < 8; j++)
#pragma unroll
        for (int e = 0; e < 4; e++) oc[j][e] = 0.f;
#pragma unroll
    for (int e = 0; e < 4; e++) ls[e] = 0.f;
    float m0 = -1e30f, m1 = -1e30f;

    const int trow0 = q0 + wid * 16 + (lane >> 2);
    const uint32_t ONE2 = 0x3C003C00u;        // (1.0h, 1.0h)
    const uint32_t ones_b[2] = {ONE2, ONE2};

    for (int jt = 0; jt < JT; jt++) {
        if (jt + 1 < JT) asm volatile("cp.async.wait_group 1;" ::: "memory");
        else             asm volatile("cp.async.wait_group 0;" ::: "memory");
        __syncthreads();
        const uint32_t S = (jt & 1) ? ST1 : ST0;

        // scores: 16 j-frags x 128 kv cols, log2 domain
        float sc[16][4];
#pragma unroll
        for (int j = 0; j < 16; j++)
#pragma unroll
            for (int e = 0; e < 4; e++) sc[j][e] = 0.f;
#pragma unroll
        for (int kk = 0; kk < 4; kk++) {
            uint32_t kf[8][4];
#pragma unroll
            for (int p = 0; p < 8; p++)
                ldsm4(kf[p], S + swz((p * 16 + bRowOff) * 128 + kk * 32 + bKHalf));
#pragma unroll
            for (int j = 0; j < 16; j++)
                mma16816(sc[j], qa[kk], &kf[j >> 1][(j & 1) * 2]);
        }

        if (jt == JT - 1) {                // diagonal tile: causal mask
            int s0c = jt << 7;
#pragma unroll
            for (int j = 0; j < 16; j++) {
                int scol = s0c + 8 * j + ((lane & 3) << 1);
                if (scol     > trow0)     sc[j][0] = -1e30f;
                if (scol + 1 > trow0)     sc[j][1] = -1e30f;
                if (scol     > trow0 + 8) sc[j][2] = -1e30f;
                if (scol + 1 > trow0 + 8) sc[j][3] = -1e30f;
            }
        }

        // row max (base-2 domain)
        float r0 = -1e30f, r1 = -1e30f;
#pragma unroll
        for (int j = 0; j < 16; j++) {
            r0 = fmaxf(r0, fmaxf(sc[j][0], sc[j][1]));
            r1 = fmaxf(r1, fmaxf(sc[j][2], sc[j][3]));
        }
        r0 = fmaxf(r0, __shfl_xor_sync(0xffffffffu, r0, 1));
        r0 = fmaxf(r0, __shfl_xor_sync(0xffffffffu, r0, 2));
        r1 = fmaxf(r1, __shfl_xor_sync(0xffffffffu, r1, 1));
        r1 = fmaxf(r1, __shfl_xor_sync(0xffffffffu, r1, 2));
        float mn0 = fmaxf(m0, r0), mn1 = fmaxf(m1, r1);
        float a0 = ex2(m0 - mn0), a1 = ex2(m1 - mn1);
        m0 = mn0; m1 = mn1;

        // P = ex2(sc - mn) directly in f16x2 A-frag layout
        uint32_t ph[16][2];
#pragma unroll
        for (int j = 0; j < 16; j++) {
            ph[j][0] = ex2_pack(sc[j][0] - mn0, sc[j][1] - mn0);
            ph[j][1] = ex2_pack(sc[j][2] - mn1, sc[j][3] - mn1);
        }

        // rescale accumulators (ls[1], ls[3] are duplicate columns, unread)
        ls[0] *= a0; ls[2] *= a1;
#pragma unroll
        for (int j = 0; j < 8; j++) {
            oc[j][0] *= a0; oc[j][1] *= a0; oc[j][2] *= a1; oc[j][3] *= a1;
        }

        // PV + ones-column row-sum: 8 k16 steps
#pragma unroll
        for (int kc = 0; kc < 8; kc++) {
            uint32_t pah[4] = {ph[2*kc][0], ph[2*kc][1], ph[2*kc+1][0], ph[2*kc+1][1]};
            uint32_t vf[4][4];
#pragma unroll
            for (int p = 0; p < 4; p++)
                ldsm4t(vf[p], S + 16384 +
                       swz((kc * 16 + aRowOff) * 128 + p * 32 + aKHalf));
#pragma unroll
            for (int j = 0; j < 8; j++)
                mma16816(oc[j], pah, &vf[j >> 1][(j & 1) * 2]);
            mma16816(ls, pah, ones_b);     // row sum of P (full k-reduction)
        }
        __syncthreads();                   // all warps done with stage jt&1
        if (jt + 2 < JT) load_kv(jt + 2);
    }

    // Epilogue: normalize -> single-plane fp16 atts [4096,1024]
    float i0 = 1.f / ls[0], i1 = 1.f / ls[2];
    size_t rA = (size_t)(b * TT + trow0) * DDIM + h * HDD;
    size_t rB = rA + (size_t)8 * DDIM;
#pragma unroll
    for (int j = 0; j < 8; j++) {
        int col = 8 * j + ((lane & 3) << 1);
        __half2 oA{__float2half_rn(oc[j][0] * i0), __float2half_rn(oc[j][1] * i0)};
        __half2 oB{__float2half_rn(oc[j][2] * i1), __float2half_rn(oc[j][3] * i1)};
        *(uint32_t*)(Oout + rA + col) = *(uint32_t*)&oA;
        *(uint32_t*)(Oout + rB + col) = *(uint32_t*)&oB;
    }
}

// ---------------------------------------------------------------------------
extern "C" void kernel_launch(void* const* d_in, const int* in_sizes, int n_in,
                              void* d_out, int out_size) {
    const float* x  = (const float*)d_in[0];
    const float* Wq = (const float*)d_in[1];
    const float* Wk = (const float*)d_in[2];
    const float* Wv = (const float*)d_in[3];
    const float* Wo = (const float*)d_in[4];
    float* out = (float*)d_out;

    __half *xh, *ats, *w16, *wo16, *qp, *kp, *vp;
    cudaGetSymbolAddress((void**)&xh, g_xh);
    cudaGetSymbolAddress((void**)&ats, g_atts);
    cudaGetSymbolAddress((void**)&w16, g_w16);
    cudaGetSymbolAddress((void**)&wo16, g_wo16);
    cudaGetSymbolAddress((void**)&qp, g_qp);
    cudaGetSymbolAddress((void**)&kp, g_kp);
    cudaGetSymbolAddress((void**)&vp, g_vp);

    cudaFuncSetAttribute(gemm_hmma, cudaFuncAttributeMaxDynamicSharedMemorySize, GEMM_DYN);
    cudaFuncSetAttribute(attn_mma, cudaFuncAttributeMaxDynamicSharedMemorySize, ATT_DYN);

    // operand prep (all single-plane fp16)
    xconv<<<MM, 256>>>(x, xh);
    dim3 wgrid(DDIM, 4);
    wconv4<<<wgrid, 256>>>(Wq, Wk, Wv, Wo, w16, wo16);

    // merged Q/K/V projection: one launch, N=3072, K=1024
    dim3 qkvgrid(3 * DDIM / 128, MM / 128);   // (24, 32) = 768 CTAs
    gemm_hmma<<<qkvgrid, 256, GEMM_DYN>>>(xh, w16, nullptr, 3);

    dim3 agrid(TT / 64, HH, BB);              // (32, 16, 2) = 1024 CTAs
    attn_mma<<<agrid, 128, ATT_DYN>>>(qp, kp, vp, ats);

    // Wo: single-plane fp16, K=1024
    dim3 ogrid(DDIM / 128, MM / 128);         // (8, 32)
    gemm_hmma<<<ogrid, 256, GEMM_DYN>>>(ats, wo16, out, 0);
}